// round 1
// baseline (speedup 1.0000x reference)
#include <cuda_runtime.h>

// crossCorrelation3D: local 9x9 windowed cross-correlation loss.
// input:  (32,1,512,512) fp32   target: (32,1,512,512) fp32
// out: scalar = -mean( cross^2 / (T_var*I_var + 1e-5) )
//
// cross = IT_sum - I_sum*T_sum/81 ; T_var = TT_sum - T_sum^2/81 ; I_var likewise.
// Separable 9x9 box sums via horizontal sliding sums + vertical running sums
// (9-deep hsum ring in shared, thread-private columns).

#define IMG_W 512
#define IMG_H 512
#define NBATCH 32
#define HT 64               // output rows per block
#define NTHREADS 128        // threads per block, VEC=4 cols each -> 512 cols
#define RING_F (9*5*512)    // 9 rows x 5 channels x 512 cols
#define ROWBUF 528          // 4 left pad + 512 data + 4 right pad + align pad
#define NPART (8*32)        // gridDim.x * gridDim.y

__device__ float g_part[NPART];

__device__ __forceinline__ void hsum9(const float* v, float* h) {
    float s = ((v[0] + v[1]) + (v[2] + v[3])) +
              ((v[4] + v[5]) + (v[6] + v[7])) + v[8];
    h[0] = s;
    s = s - v[0] + v[9];  h[1] = s;
    s = s - v[1] + v[10]; h[2] = s;
    s = s - v[2] + v[11]; h[3] = s;
}

__device__ __forceinline__ float ccval(float sI, float sT, float sII, float sTT, float sIT) {
    const float inv = 1.0f / 81.0f;
    float cross = fmaf(-(sI * sT), inv, sIT);
    float tvar  = fmaf(-(sT * sT), inv, sTT);
    float ivar  = fmaf(-(sI * sI), inv, sII);
    float den   = fmaf(tvar, ivar, 1e-5f);
    return (cross * cross) / den;
}

__global__ __launch_bounds__(NTHREADS)
void cc_kernel(const float* __restrict__ inp, const float* __restrict__ tgt) {
    extern __shared__ float sm[];
    float* ring = sm;             // RING_F floats
    float* rows = sm + RING_F;    // 4 * ROWBUF floats: I0, I1, T0, T1

    const int tid = threadIdx.x;
    const int bx  = blockIdx.x;   // ytile 0..7
    const int b   = blockIdx.y;   // batch 0..31
    const int y0  = bx * HT;

    const float* Ib = inp + (size_t)b * IMG_H * IMG_W;
    const float* Tb = tgt + (size_t)b * IMG_H * IMG_W;

    // zero ring (thread-private columns)
    {
        float4 z = make_float4(0.f, 0.f, 0.f, 0.f);
        #pragma unroll
        for (int r = 0; r < 9; r++)
            #pragma unroll
            for (int c = 0; c < 5; c++)
                *(float4*)&ring[(r * 5 + c) * 512 + 4 * tid] = z;
    }
    // zero horizontal pads of the 4 row buffers
    if (tid < 16) {
        int bufi = tid >> 2, j = tid & 3;
        rows[bufi * ROWBUF + j] = 0.f;
        rows[bufi * ROWBUF + 516 + j] = 0.f;
    }

    float4 vI  = make_float4(0.f,0.f,0.f,0.f);
    float4 vT  = vI, vII = vI, vTT = vI, vIT = vI;
    float acc = 0.f;
    int rpos = 0;

    const float4 z4 = make_float4(0.f,0.f,0.f,0.f);

    // prefetch first input row yi = y0-4 (normalize T at load; zeros if OOR)
    float4 pI, pT;
    {
        int yn = y0 - 4;
        if (yn >= 0) {
            pI = *(const float4*)&Ib[(size_t)yn * IMG_W + 4 * tid];
            float4 t = *(const float4*)&Tb[(size_t)yn * IMG_W + 4 * tid];
            pT.x = fmaf(t.x, 0.5f, 0.5f);
            pT.y = fmaf(t.y, 0.5f, 0.5f);
            pT.z = fmaf(t.z, 0.5f, 0.5f);
            pT.w = fmaf(t.w, 0.5f, 0.5f);
        } else { pI = z4; pT = z4; }
    }

    for (int it = 0; it < HT + 8; ++it) {
        const int yi = y0 - 4 + it;
        float* sI = rows + (it & 1) * ROWBUF;
        float* sT = rows + (2 + (it & 1)) * ROWBUF;

        // stage current row (data region idx 4..515)
        *(float4*)&sI[4 * tid + 4] = pI;
        *(float4*)&sT[4 * tid + 4] = pT;
        __syncthreads();

        // prefetch next row
        {
            int yn = yi + 1;
            if (yn >= 0 && yn < IMG_H && (it + 1) < HT + 8) {
                pI = *(const float4*)&Ib[(size_t)yn * IMG_W + 4 * tid];
                float4 t = *(const float4*)&Tb[(size_t)yn * IMG_W + 4 * tid];
                pT.x = fmaf(t.x, 0.5f, 0.5f);
                pT.y = fmaf(t.y, 0.5f, 0.5f);
                pT.z = fmaf(t.z, 0.5f, 0.5f);
                pT.w = fmaf(t.w, 0.5f, 0.5f);
            } else { pI = z4; pT = z4; }
        }

        // load 12 I and 12 t values (cols 4t-4 .. 4t+7)
        float iv[12], tv[12];
        #pragma unroll
        for (int k = 0; k < 3; k++) {
            float4 a = *(float4*)&sI[4 * tid + 4 * k];
            float4 c = *(float4*)&sT[4 * tid + 4 * k];
            iv[4*k+0] = a.x; iv[4*k+1] = a.y; iv[4*k+2] = a.z; iv[4*k+3] = a.w;
            tv[4*k+0] = c.x; tv[4*k+1] = c.y; tv[4*k+2] = c.z; tv[4*k+3] = c.w;
        }

        float pII[12], pTT[12], pIT[12];
        #pragma unroll
        for (int j = 0; j < 12; j++) {
            pII[j] = iv[j] * iv[j];
            pTT[j] = tv[j] * tv[j];
            pIT[j] = iv[j] * tv[j];
        }

        float hI[4], hT[4], hII[4], hTT[4], hIT[4];
        hsum9(iv,  hI);
        hsum9(tv,  hT);
        hsum9(pII, hII);
        hsum9(pTT, hTT);
        hsum9(pIT, hIT);

        // ring update + vertical running sums (thread-private, no sync)
        float* rb = ring + rpos * (5 * 512) + 4 * tid;
        float4 o;
        o = *(float4*)&rb[0];
        vI.x += hI[0] - o.x;  vI.y += hI[1] - o.y;  vI.z += hI[2] - o.z;  vI.w += hI[3] - o.w;
        *(float4*)&rb[0] = make_float4(hI[0], hI[1], hI[2], hI[3]);
        o = *(float4*)&rb[512];
        vT.x += hT[0] - o.x;  vT.y += hT[1] - o.y;  vT.z += hT[2] - o.z;  vT.w += hT[3] - o.w;
        *(float4*)&rb[512] = make_float4(hT[0], hT[1], hT[2], hT[3]);
        o = *(float4*)&rb[1024];
        vII.x += hII[0] - o.x; vII.y += hII[1] - o.y; vII.z += hII[2] - o.z; vII.w += hII[3] - o.w;
        *(float4*)&rb[1024] = make_float4(hII[0], hII[1], hII[2], hII[3]);
        o = *(float4*)&rb[1536];
        vTT.x += hTT[0] - o.x; vTT.y += hTT[1] - o.y; vTT.z += hTT[2] - o.z; vTT.w += hTT[3] - o.w;
        *(float4*)&rb[1536] = make_float4(hTT[0], hTT[1], hTT[2], hTT[3]);
        o = *(float4*)&rb[2048];
        vIT.x += hIT[0] - o.x; vIT.y += hIT[1] - o.y; vIT.z += hIT[2] - o.z; vIT.w += hIT[3] - o.w;
        *(float4*)&rb[2048] = make_float4(hIT[0], hIT[1], hIT[2], hIT[3]);
        rpos = (rpos == 8) ? 0 : rpos + 1;

        if (it >= 8) {
            acc += ccval(vI.x, vT.x, vII.x, vTT.x, vIT.x);
            acc += ccval(vI.y, vT.y, vII.y, vTT.y, vIT.y);
            acc += ccval(vI.z, vT.z, vII.z, vTT.z, vIT.z);
            acc += ccval(vI.w, vT.w, vII.w, vTT.w, vIT.w);
        }
    }

    // deterministic block reduction (reuse row buffers)
    __syncthreads();
    rows[tid] = acc;
    __syncthreads();
    #pragma unroll
    for (int s = NTHREADS / 2; s > 0; s >>= 1) {
        if (tid < s) rows[tid] += rows[tid + s];
        __syncthreads();
    }
    if (tid == 0) g_part[b * 8 + bx] = rows[0];
}

__global__ void fin_kernel(float* __restrict__ out) {
    __shared__ float s[NPART];
    int t = threadIdx.x;
    s[t] = g_part[t];
    __syncthreads();
    #pragma unroll
    for (int k = NPART / 2; k > 0; k >>= 1) {
        if (t < k) s[t] += s[t + k];
        __syncthreads();
    }
    if (t == 0) out[0] = -s[0] * (1.0f / 8388608.0f);
}

extern "C" void kernel_launch(void* const* d_in, const int* in_sizes, int n_in,
                              void* d_out, int out_size) {
    const float* inp = (const float*)d_in[0];
    const float* tgt = (const float*)d_in[1];
    size_t smem = (size_t)(RING_F + 4 * ROWBUF) * sizeof(float);  // ~100.6 KB
    cudaFuncSetAttribute(cc_kernel, cudaFuncAttributeMaxDynamicSharedMemorySize, (int)smem);
    dim3 grid(IMG_H / HT, NBATCH);   // (8, 32) = 256 blocks
    cc_kernel<<<grid, NTHREADS, smem>>>(inp, tgt);
    fin_kernel<<<1, NPART>>>((float*)d_out);
}